// round 16
// baseline (speedup 1.0000x reference)
#include <cuda_runtime.h>

// ============================================================================
// TorusConv3D via FFT diagonalization (round 16).
// Round-16: phase-1 global loads pinned with asm volatile ld.global.nc.b64
// (R15's C-level batching was re-serialized by ptxas: regs stayed 32). All 16
// loads now issue before the first butterfly -> true per-thread MLP=16 in fwd
// and ifft. Pointwise (R14 P/Q winner) and all layouts unchanged.
// ============================================================================

typedef unsigned long long ull;

// Packed spectra: g_Xp[k*2048 + b*32 + j], g_Wp[k*2048 + f*32 + j],
//                 g_Z [k*2048 + b*32 + fp]
__device__ ull g_Xp[512 * 2048];
__device__ ull g_Wp[512 * 2048];
__device__ ull g_Z[512 * 2048];

// ---------------------------------------------------------------------------
// Packed f32x2 primitives. A complex value is (re, im) = (lo, hi) of an ull.
// ---------------------------------------------------------------------------
__device__ __forceinline__ ull pk(float lo, float hi) {
    ull r;
    asm("mov.b64 %0, {%1, %2};" : "=l"(r) : "f"(lo), "f"(hi));
    return r;
}
__device__ __forceinline__ void upk(ull v, float& lo, float& hi) {
    asm("mov.b64 {%0, %1}, %2;" : "=f"(lo), "=f"(hi) : "l"(v));
}
__device__ __forceinline__ ull add2(ull a, ull b) {
    ull d;
    asm("add.rn.f32x2 %0, %1, %2;" : "=l"(d) : "l"(a), "l"(b));
    return d;
}
__device__ __forceinline__ ull mul2(ull a, ull b) {
    ull d;
    asm("mul.rn.f32x2 %0, %1, %2;" : "=l"(d) : "l"(a), "l"(b));
    return d;
}
__device__ __forceinline__ ull fma2(ull a, ull b, ull c) {
    ull d;
    asm("fma.rn.f32x2 %0, %1, %2, %3;" : "=l"(d) : "l"(a), "l"(b), "l"(c));
    return d;
}
__device__ __forceinline__ ull sub2(ull a, ull b) {
    return fma2(b, 0xBF800000BF800000ULL, a);  // a + (-1)*b
}
__device__ __forceinline__ float negf(float x) {
    return __uint_as_float(__float_as_uint(x) ^ 0x80000000u);
}
template <int INV>
__device__ __forceinline__ ull mi(ull a) {  // *(-i) fwd, *(+i) inv
    float x, y;
    upk(a, x, y);
    return INV ? pk(negf(y), x) : pk(y, negf(x));
}

// Pinned 8-byte global load (issue order preserved by asm volatile).
__device__ __forceinline__ ull ldg64(const void* p) {
    ull v;
    asm volatile("ld.global.nc.b64 %0, [%1];" : "=l"(v) : "l"(p));
    return v;
}

#define R2R2 0x3F3504F33F3504F3ULL  // (sqrt(0.5), sqrt(0.5))

template <int INV>
__device__ __forceinline__ void fft8p(ull* v) {
    ull t0 = add2(v[0], v[4]), t1 = sub2(v[0], v[4]);
    ull t2 = add2(v[2], v[6]), t3 = sub2(v[2], v[6]);
    ull t4 = add2(v[1], v[5]), t5 = sub2(v[1], v[5]);
    ull t6 = add2(v[3], v[7]), t7 = sub2(v[3], v[7]);
    ull a0 = add2(t0, t2), a1 = sub2(t0, t2);
    ull m3 = mi<INV>(t3);
    ull a2 = add2(t1, m3), a3 = sub2(t1, m3);
    ull b0 = add2(t4, t6), b1 = sub2(t4, t6);
    ull m7 = mi<INV>(t7);
    ull b2 = add2(t5, m7), b3 = sub2(t5, m7);
    ull mb1 = mi<INV>(b1);
    ull w1v = mul2(add2(b2, mi<INV>(b2)), R2R2);
    ull w3v = mi<INV>(mul2(add2(b3, mi<INV>(b3)), R2R2));
    v[0] = add2(a0, b0); v[4] = sub2(a0, b0);
    v[2] = add2(a1, mb1); v[6] = sub2(a1, mb1);
    v[1] = add2(a2, w1v); v[5] = sub2(a2, w1v);
    v[3] = add2(a3, w3v); v[7] = sub2(a3, w3v);
}

// ---------------------------------------------------------------------------
// Kernel 1: forward packed FFT, 16-column tiles, 512 threads.
// Phase 1: 16 pinned loads (MLP=16), then 2 FFTs + STS.
// Blocks [0,128) -> inputs->Xp, [128,256) -> kernel->Wp.
// ---------------------------------------------------------------------------
__global__ void __launch_bounds__(512)
fft3d_fwd_packed(const float* __restrict__ inA, const float* __restrict__ inB,
                 ull* __restrict__ outA, ull* __restrict__ outB) {
    extern __shared__ ull V[];
    int blk = blockIdx.x;
    const float* in;
    ull* out;
    long rowStride, sStride;
    if (blk < 128) { in = inA; out = outA; rowStride = 32768; sStride = 64; }
    else           { blk -= 128; in = inB; out = outB; rowStride = 64; sStride = 4096; }
    const int row = blk >> 1, j0 = (blk & 1) * 16;
    const int tid = threadIdx.x;
    const int c = tid & 15, pp = tid >> 4;

    const float* base = in + (long)row * rowStride + 2 * (j0 + c);

    // Phase 1: all 16 loads pinned before any butterfly.
    ull d[16];
#pragma unroll
    for (int m = 0; m < 2; ++m) {
        const int t = pp + 32 * m;
#pragma unroll
        for (int z = 0; z < 8; ++z)
            d[m * 8 + z] = ldg64(base + (long)(8 * t + z) * sStride);
    }
#pragma unroll
    for (int m = 0; m < 2; ++m) {
        const int t = pp + 32 * m;
        fft8p<0>(d + m * 8);
#pragma unroll
        for (int z = 0; z < 8; ++z) V[(8 * t + z) * 16 + c] = d[m * 8 + z];
    }
    __syncthreads();

    // Phase 2: y-axis through smem. t = (x,z). stride 128.
    ull buf[8];
#pragma unroll
    for (int m = 0; m < 2; ++m) {
        const int t = pp + 32 * m;
        const int b0 = ((t >> 3) * 64 + (t & 7)) * 16 + c;
#pragma unroll
        for (int y = 0; y < 8; ++y) buf[y] = V[b0 + y * 128];
        fft8p<0>(buf);
#pragma unroll
        for (int y = 0; y < 8; ++y) V[b0 + y * 128] = buf[y];
    }
    __syncthreads();

    // Phase 3: x-axis fused with global store. t = (ky,kz). stride 1024.
    ull* og = out + row * 32 + j0 + c;
#pragma unroll
    for (int m = 0; m < 2; ++m) {
        const int t = pp + 32 * m;
#pragma unroll
        for (int x = 0; x < 8; ++x) buf[x] = V[t * 16 + c + x * 1024];
        fft8p<0>(buf);
#pragma unroll
        for (int x = 0; x < 8; ++x) og[(long)(x * 64 + t) * 2048] = buf[x];
    }
}

// ---------------------------------------------------------------------------
// Kernel 2: Hermitian pointwise complex GEMM (round-14 winner, unchanged).
// 260 canonical freqs, 512 threads, 2(b) x 4(f) tiles, P/Q accumulation.
// ---------------------------------------------------------------------------
__global__ void __launch_bounds__(512)
pointwise_kernel(float2* __restrict__ Zh) {
    const int rank = blockIdx.x;
    int kx, ky, kz;
    if (rank < 192) {
        kx = 1 + rank / 64; const int r = rank & 63; ky = r >> 3; kz = r & 7;
    } else if (rank < 240) {
        const int r = rank - 192; kx = (r / 24) * 4;
        const int r2 = r % 24; ky = 1 + r2 / 8; kz = r2 & 7;
    } else {
        const int r = rank - 240; kx = (r / 10) * 4;
        const int r2 = r % 10; ky = (r2 / 5) * 4; kz = r2 % 5;
    }
    const int k = (kx << 6) | (ky << 3) | kz;
    const int neg = (((8 - kx) & 7) << 6) | (((8 - ky) & 7) << 3) | ((8 - kz) & 7);

    extern __shared__ float2 sm[];
    float2* As = sm;            // [c][b], stride 65
    float2* Bs = sm + 64 * 65;  // [c][f], stride 65
    const int tid = threadIdx.x;

    const float2* xk = (const float2*)g_Xp + (long)k * 2048;
    const float2* xn = (const float2*)g_Xp + (long)neg * 2048;
    const float2* wk = (const float2*)g_Wp + (long)k * 2048;
    const float2* wn = (const float2*)g_Wp + (long)neg * 2048;
    for (int i = tid; i < 2048; i += 512) {
        const int j = i & 31, rowi = i >> 5;
        const int c0 = 2 * j, c1 = 2 * j + 1;
        {
            const float2 Pk = xk[i], Pn = xn[i];
            As[c0 * 65 + rowi] = make_float2(0.5f * (Pk.x + Pn.x), 0.5f * (Pk.y - Pn.y));
            As[c1 * 65 + rowi] = make_float2(0.5f * (Pk.y + Pn.y), 0.5f * (Pn.x - Pk.x));
        }
        {
            const float2 Pk = wk[i], Pn = wn[i];
            Bs[c0 * 65 + rowi] = make_float2(0.5f * (Pk.x + Pn.x), 0.5f * (Pk.y - Pn.y));
            Bs[c1 * 65 + rowi] = make_float2(0.5f * (Pk.y + Pn.y), 0.5f * (Pn.x - Pk.x));
        }
    }
    __syncthreads();

    const int ft = tid & 15;   // f = ft + 16j
    const int bt = tid >> 4;   // b = bt + 32i
    ull accP[2][4], accQ[2][4];
#pragma unroll
    for (int i = 0; i < 2; ++i)
#pragma unroll
        for (int j = 0; j < 4; ++j) { accP[i][j] = 0ULL; accQ[i][j] = 0ULL; }

    ull axx[2], ayy[2], bv[4];
#pragma unroll 4
    for (int cc = 0; cc < 64; ++cc) {
#pragma unroll
        for (int i = 0; i < 2; ++i) {
            const float2 t = As[cc * 65 + bt + 32 * i];
            axx[i] = pk(t.x, t.x);
            ayy[i] = pk(t.y, t.y);
        }
#pragma unroll
        for (int j = 0; j < 4; ++j)
            bv[j] = *(const ull*)&Bs[cc * 65 + ft + 16 * j];  // (bx, by) raw
#pragma unroll
        for (int i = 0; i < 2; ++i)
#pragma unroll
            for (int j = 0; j < 4; ++j) {
                accP[i][j] = fma2(axx[i], bv[j], accP[i][j]);  // (ax*bx, ax*by)
                accQ[i][j] = fma2(ayy[i], bv[j], accQ[i][j]);  // (ay*bx, ay*by)
            }
    }

    // Fixup + drain: Y = (P.lo - Q.hi, P.hi + Q.lo); pack f-pairs via shfl.
    float2* zk = Zh + (long)k * 2048;
    float2* zn = Zh + (long)neg * 2048;
    const bool self = (k == neg);
    const bool even = (ft & 1) == 0;
    const int fp0 = ft >> 1;
#pragma unroll
    for (int i = 0; i < 2; ++i)
#pragma unroll
        for (int j = 0; j < 4; ++j) {
            float px, py, qx, qy;
            upk(accP[i][j], px, py);
            upk(accQ[i][j], qx, qy);
            const ull y = pk(px - qy, py + qx);  // (Y.re, Y.im)
            const ull part = __shfl_xor_sync(0xffffffffu, y, 1);
            if (even) {
                float y0x, y0y, y1x, y1y;
                upk(y, y0x, y0y);      // f = 2fp
                upk(part, y1x, y1y);   // f = 2fp+1
                const int idx = (bt + 32 * i) * 32 + fp0 + 8 * j;
                zk[idx] = make_float2(y0x - y1y, y0y + y1x);
                if (!self) zn[idx] = make_float2(y0x + y1y, y1x - y0y);
            }
        }
}

// ---------------------------------------------------------------------------
// Kernel 3: inverse packed FFT + bias, 16-column tiles, 512 threads, grid 128.
// Phase 1: 16 pinned loads of Z before compute.
// IFFT(Y_{2f}+iY_{2f+1}) = out_{2f} + i out_{2f+1}.
// ---------------------------------------------------------------------------
__global__ void __launch_bounds__(512)
ifft3d_packed(const ull* __restrict__ Zh, const float* __restrict__ bias,
              float* __restrict__ out) {
    extern __shared__ ull V[];
    const int b = blockIdx.x >> 1, fp0 = (blockIdx.x & 1) * 16;
    const int tid = threadIdx.x;
    const int c = tid & 15, pp = tid >> 4;
    const float2 bv = ((const float2*)bias)[fp0 + c];

    const ull* yg = Zh + b * 32 + fp0 + c;

    // Phase 1: all 16 loads pinned before any butterfly.
    ull d[16];
#pragma unroll
    for (int m = 0; m < 2; ++m) {
        const int t = pp + 32 * m;
#pragma unroll
        for (int z = 0; z < 8; ++z)
            d[m * 8 + z] = ldg64(yg + (long)(8 * t + z) * 2048);
    }
#pragma unroll
    for (int m = 0; m < 2; ++m) {
        const int t = pp + 32 * m;
        fft8p<1>(d + m * 8);
#pragma unroll
        for (int z = 0; z < 8; ++z) V[(8 * t + z) * 16 + c] = d[m * 8 + z];
    }
    __syncthreads();

    // Phase 2: y-axis.
    ull buf[8];
#pragma unroll
    for (int m = 0; m < 2; ++m) {
        const int t = pp + 32 * m;
        const int b0 = ((t >> 3) * 64 + (t & 7)) * 16 + c;
#pragma unroll
        for (int y = 0; y < 8; ++y) buf[y] = V[b0 + y * 128];
        fft8p<1>(buf);
#pragma unroll
        for (int y = 0; y < 8; ++y) V[b0 + y * 128] = buf[y];
    }
    __syncthreads();

    // Phase 3: x-axis fused with store (re -> 2fp, im -> 2fp+1, +bias).
    float2* og = (float2*)out + (long)b * 512 * 32 + fp0 + c;
#pragma unroll
    for (int m = 0; m < 2; ++m) {
        const int t = pp + 32 * m;
#pragma unroll
        for (int x = 0; x < 8; ++x) buf[x] = V[t * 16 + c + x * 1024];
        fft8p<1>(buf);
#pragma unroll
        for (int x = 0; x < 8; ++x) {
            float re, im;
            upk(buf[x], re, im);
            og[(long)(x * 64 + t) * 32] =
                make_float2(re * (1.f / 512.f) + bv.x, im * (1.f / 512.f) + bv.y);
        }
    }
}

// ---------------------------------------------------------------------------
extern "C" void kernel_launch(void* const* d_in, const int* in_sizes, int n_in,
                              void* d_out, int out_size) {
    const float* inputs = (const float*)d_in[0];
    const float* kern   = (const float*)d_in[1];
    const float* bias   = (const float*)d_in[2];
    float* out = (float*)d_out;

    ull *Xp, *Wp, *Zh;
    cudaGetSymbolAddress((void**)&Xp, g_Xp);
    cudaGetSymbolAddress((void**)&Wp, g_Wp);
    cudaGetSymbolAddress((void**)&Zh, g_Z);

    const int smemFFT = 512 * 16 * (int)sizeof(ull);       // 65536 B
    const int smemPW  = 2 * 64 * 65 * (int)sizeof(float2); // 66560 B
    cudaFuncSetAttribute(fft3d_fwd_packed, cudaFuncAttributeMaxDynamicSharedMemorySize, smemFFT);
    cudaFuncSetAttribute(ifft3d_packed,    cudaFuncAttributeMaxDynamicSharedMemorySize, smemFFT);
    cudaFuncSetAttribute(pointwise_kernel, cudaFuncAttributeMaxDynamicSharedMemorySize, smemPW);

    fft3d_fwd_packed<<<256, 512, smemFFT>>>(inputs, kern, Xp, Wp);
    pointwise_kernel<<<260, 512, smemPW>>>((float2*)Zh);
    ifft3d_packed<<<128, 512, smemFFT>>>(Zh, bias, out);
}